// round 3
// baseline (speedup 1.0000x reference)
#include <cuda_runtime.h>
#include <math.h>

// Problem constants (fixed-shape problem)
#define BB   16
#define NN   2048
#define DD   64
#define EE   32768
#define MAXK 128
#define ROWS (BB*NN)          // 32768
#define TBL  128

// Scratch (device globals; no allocation anywhere)
__device__ int      g_cnt[ROWS];
__device__ uint2    g_bucket[(size_t)ROWS * MAXK];   // 32 MB (col<<17|pri, m_bits)
__device__ float    g_dis[ROWS];
__device__ float    g_diag[ROWS];
__device__ uint2    g_adj[(size_t)ROWS * MAXK];      // 32 MB (col, w_bits)
__device__ float    g_x1[(size_t)ROWS * DD];         // 8 MB ping buffer

// ---------------------------------------------------------------------------
__global__ void zero_cnt_k() {
    int t = blockIdx.x * blockDim.x + threadIdx.x;
    if (t < ROWS) g_cnt[t] = 0;
}

// ---------------------------------------------------------------------------
// scatter directed entries into per-row buckets, carrying m along (coalesced
// m read here so no later pass ever gathers m again).
// key = (col << 17) | priority, priority = pass*E + e (pass2 > pass1)
__global__ void scatter_k(const int* __restrict__ ei, const float* __restrict__ m) {
    int t = blockIdx.x * blockDim.x + threadIdx.x;
    if (t >= BB * EE) return;
    int b = t >> 15;
    int e = t & (EE - 1);
    int src = ei[b * 2 * EE + e];
    int dst = ei[b * 2 * EE + EE + e];
    unsigned mbits = __float_as_uint(m[b * EE + e]);   // coalesced

    int r1 = b * NN + src;
    int p1 = atomicAdd(&g_cnt[r1], 1);
    if (p1 < MAXK)
        g_bucket[(size_t)r1 * MAXK + p1] = make_uint2(((unsigned)dst << 17) | (unsigned)e, mbits);

    int r2 = b * NN + dst;
    int p2 = atomicAdd(&g_cnt[r2], 1);
    if (p2 < MAXK)
        g_bucket[(size_t)r2 * MAXK + p2] = make_uint2(((unsigned)src << 17) | (unsigned)(EE + e), mbits);
}

// ---------------------------------------------------------------------------
// O(k) hash dedup: per-row 128-slot smem table, 64-bit atomicMax keyed on
// (col<<17|pri) in the high word (exact .set last-write-wins). Ballot
// compaction writes (col, m_bits) to g_adj; degree -> dis = rsqrt(deg).
// One warp per row, 8 rows per block.
__global__ void __launch_bounds__(256) dedup_k() {
    __shared__ unsigned long long tbl[8][TBL];
    int wid  = threadIdx.x >> 5, lane = threadIdx.x & 31;
    int row  = blockIdx.x * 8 + wid;

    for (int i = lane; i < TBL; i += 32) tbl[wid][i] = 0ULL;
    __syncwarp();

    int k = g_cnt[row];
    if (k > MAXK) k = MAXK;
    const uint2* src = &g_bucket[(size_t)row * MAXK];
    for (int t = lane; t < k; t += 32) {
        uint2 v = src[t];
        unsigned col = v.x >> 17;
        unsigned long long val = ((unsigned long long)v.x << 32) | (unsigned long long)v.y;
        unsigned h = col & (TBL - 1);
        while (true) {
            unsigned long long cur = tbl[wid][h];
            if (cur == 0ULL) {
                unsigned long long old = atomicCAS(&tbl[wid][h], 0ULL, val);
                if (old == 0ULL) break;
                cur = old;
            }
            if ((unsigned)(cur >> 49) == col) {       // same col -> keep max priority
                atomicMax(&tbl[wid][h], val);
                break;
            }
            h = (h + 1) & (TBL - 1);
        }
    }
    __syncwarp();

    // compact + degree sum
    float deg = 0.f;
    int base = 0;
    uint2* dst = &g_adj[(size_t)row * MAXK];
    #pragma unroll
    for (int s0 = 0; s0 < TBL; s0 += 32) {
        unsigned long long cur = tbl[wid][s0 + lane];
        bool has = (cur != 0ULL);
        unsigned bal = __ballot_sync(0xFFFFFFFFu, has);
        if (has) {
            int pos = base + __popc(bal & ((1u << lane) - 1));
            unsigned col = ((unsigned)(cur >> 32)) >> 17;
            unsigned mb  = (unsigned)cur;
            dst[pos] = make_uint2(col, mb);
            deg += __uint_as_float(mb);
        }
        base += __popc(bal);
    }
    #pragma unroll
    for (int o = 16; o; o >>= 1) deg += __shfl_down_sync(0xFFFFFFFFu, deg, o);
    if (lane == 0) {
        g_cnt[row] = base;
        g_dis[row] = rsqrtf(fmaxf(1.0f + deg, 1e-6f));
    }
}

// ---------------------------------------------------------------------------
// finalize: w = m * dis[row] * dis[col], streaming over compacted CSR.
// One warp per row.
__global__ void __launch_bounds__(256) finalize_k() {
    int row  = blockIdx.x * 8 + (threadIdx.x >> 5);
    int lane = threadIdx.x & 31;
    int nb   = row & ~(NN - 1);
    int nnz  = g_cnt[row];
    float disr = g_dis[row];
    uint2* adj = &g_adj[(size_t)row * MAXK];
    for (int t = lane; t < nnz; t += 32) {
        uint2 v = adj[t];
        float w = __uint_as_float(v.y) * disr * g_dis[nb + v.x];
        adj[t] = make_uint2(v.x, __float_as_uint(w));
    }
    if (lane == 0) g_diag[row] = disr * disr;
}

// ---------------------------------------------------------------------------
// fused layer: x1 = A_norm @ X (sparse + diag), out = x1 @ W^T, optional GELU.
// Warp per 4 rows, rows INTERLEAVED in the gather k-loop and unrolled x2
// -> 8 independent L2-hit load chains in flight.
__global__ void __launch_bounds__(256) layer_k(const float* __restrict__ Xin_p,
                                               const float* __restrict__ Wl,
                                               float* __restrict__ Xout_p,
                                               int apply_gelu) {
    const float* Xin  = Xin_p  ? Xin_p  : g_x1;
    float*       Xout = Xout_p ? Xout_p : g_x1;

    // sW[d*32 + j] = {W[2j][d], W[2j+1][d]}
    __shared__ float2 sW[64 * 32];
    int tid = threadIdx.x;
    for (int idx = tid; idx < 4096; idx += 256) {
        int e = idx >> 6, d = idx & 63;
        ((float*)&sW[d * 32 + (e >> 1)])[e & 1] = Wl[idx];  // coalesced read
    }
    __syncthreads();

    int wid = tid >> 5, lane = tid & 31;
    int row0 = blockIdx.x * 32 + wid * 4;
    // whole block is within one batch (2048 % 32 == 0)
    const float2* Xb = (const float2*)(Xin + (size_t)(row0 & ~(NN - 1)) * DD);

    int nnz[4];
    const uint2* adj[4];
    float2 a[4];
    int kmax = 0;
    #pragma unroll
    for (int r = 0; r < 4; r++) {
        int row = row0 + r;
        nnz[r] = g_cnt[row];
        kmax = max(kmax, nnz[r]);
        adj[r] = &g_adj[(size_t)row * MAXK];
        float dg = g_diag[row];
        float2 xo = ((const float2*)(Xin + (size_t)row * DD))[lane];
        a[r].x = dg * xo.x;
        a[r].y = dg * xo.y;
    }

    for (int k = 0; k < kmax; k += 2) {
        uint2 e[4][2];
        #pragma unroll
        for (int r = 0; r < 4; r++)
            #pragma unroll
            for (int j = 0; j < 2; j++) {
                int idx = k + j;
                idx = (idx < nnz[r]) ? idx : 0;
                e[r][j] = __ldg(&adj[r][idx]);
            }
        float2 x[4][2];
        #pragma unroll
        for (int r = 0; r < 4; r++)
            #pragma unroll
            for (int j = 0; j < 2; j++) {
                unsigned c = e[r][j].x & (NN - 1);     // safety mask
                x[r][j] = Xb[(size_t)c * 32 + lane];
            }
        #pragma unroll
        for (int r = 0; r < 4; r++)
            #pragma unroll
            for (int j = 0; j < 2; j++) {
                float w = (k + j < nnz[r]) ? __uint_as_float(e[r][j].y) : 0.f;
                a[r].x += w * x[r][j].x;
                a[r].y += w * x[r][j].y;
            }
    }

    // GEMM: out[row][e] = sum_d x1[row][d] * W[e][d]; lane owns e = {2l, 2l+1}
    float2 o[4];
    #pragma unroll
    for (int r = 0; r < 4; r++) { o[r].x = 0.f; o[r].y = 0.f; }

    #pragma unroll
    for (int d = 0; d < 64; d++) {
        float2 w2 = sW[d * 32 + lane];
        int srcl = d >> 1;
        #pragma unroll
        for (int r = 0; r < 4; r++) {
            float xd = __shfl_sync(0xFFFFFFFFu, (d & 1) ? a[r].y : a[r].x, srcl);
            o[r].x += xd * w2.x;
            o[r].y += xd * w2.y;
        }
    }

    #pragma unroll
    for (int r = 0; r < 4; r++) {
        float2 v = o[r];
        if (apply_gelu) {
            v.x = 0.5f * v.x * (1.f + erff(v.x * 0.70710678118654752f));
            v.y = 0.5f * v.y * (1.f + erff(v.y * 0.70710678118654752f));
        }
        ((float2*)(Xout + (size_t)(row0 + r) * DD))[lane] = v;
    }
}

// ---------------------------------------------------------------------------
extern "C" void kernel_launch(void* const* d_in, const int* in_sizes, int n_in,
                              void* d_out, int out_size) {
    const float* H  = (const float*)d_in[0];
    const int*   ei = (const int*)  d_in[1];
    const float* m  = (const float*)d_in[2];
    const float* W  = (const float*)d_in[3];
    float* out = (float*)d_out;

    zero_cnt_k<<<ROWS / 256, 256>>>();
    scatter_k<<<(BB * EE) / 256, 256>>>(ei, m);
    dedup_k<<<ROWS / 8, 256>>>();
    finalize_k<<<ROWS / 8, 256>>>();
    layer_k<<<ROWS / 32, 256>>>(H, W, nullptr, 1);             // layer 0 -> g_x1, GELU
    layer_k<<<ROWS / 32, 256>>>(nullptr, W + DD * DD, out, 0); // layer 1 -> out
}

// round 5
// speedup vs baseline: 1.0037x; 1.0037x over previous
#include <cuda_runtime.h>
#include <cuda_fp16.h>
#include <math.h>

// Problem constants (fixed-shape problem)
#define BB   16
#define NN   2048
#define DD   64
#define EE   32768
#define MAXK 128
#define ROWS (BB*NN)          // 32768
#define TBL  128

// Scratch (device globals; zero-initialized at module load; no allocation)
__device__ int      g_cnt_raw[ROWS];                 // scatter counters (reset by dedup)
__device__ int      g_nnz[ROWS];                     // compacted row sizes
__device__ uint2    g_bucket[(size_t)ROWS * MAXK];   // 32 MB (col<<17|pri, m_bits)
__device__ float    g_dis[ROWS];
__device__ uint2    g_adj[(size_t)ROWS * MAXK];      // 32 MB (col, m_bits)
__device__ __half2  g_xh [(size_t)ROWS * 32];        // 4 MB: dis ⊙ X (layer 0 input)
__device__ __half2  g_xh1[(size_t)ROWS * 32];        // 4 MB: dis ⊙ x1 (layer 1 input)

// ---------------------------------------------------------------------------
// scatter directed entries into per-row buckets, carrying m (coalesced read).
// key = (col << 17) | priority, priority = pass*E + e (pass2 > pass1)
__global__ void scatter_k(const int* __restrict__ ei, const float* __restrict__ m) {
    int t = blockIdx.x * blockDim.x + threadIdx.x;
    int b = t >> 15;
    int e = t & (EE - 1);
    int src = ei[b * 2 * EE + e];
    int dst = ei[b * 2 * EE + EE + e];
    unsigned mbits = __float_as_uint(m[b * EE + e]);

    int r1 = b * NN + src;
    int p1 = atomicAdd(&g_cnt_raw[r1], 1);
    if (p1 < MAXK)
        g_bucket[(size_t)r1 * MAXK + p1] = make_uint2(((unsigned)dst << 17) | (unsigned)e, mbits);

    int r2 = b * NN + dst;
    int p2 = atomicAdd(&g_cnt_raw[r2], 1);
    if (p2 < MAXK)
        g_bucket[(size_t)r2 * MAXK + p2] = make_uint2(((unsigned)src << 17) | (unsigned)(EE + e), mbits);
}

// ---------------------------------------------------------------------------
// O(k) hash dedup: per-row 128-slot smem table, 64-bit atomicMax keyed on
// (col<<17|pri) in the high word (exact .set last-write-wins). Ballot
// compaction writes (col, m_bits) to g_adj; degree -> dis = rsqrt(deg).
// Resets g_cnt_raw for the next graph replay. One warp per row, 8 rows/block.
__global__ void __launch_bounds__(256) dedup_k() {
    __shared__ unsigned long long tbl[8][TBL];
    int wid  = threadIdx.x >> 5, lane = threadIdx.x & 31;
    int row  = blockIdx.x * 8 + wid;

    for (int i = lane; i < TBL; i += 32) tbl[wid][i] = 0ULL;
    __syncwarp();

    int k = g_cnt_raw[row];
    if (k > MAXK) k = MAXK;
    const uint2* src = &g_bucket[(size_t)row * MAXK];
    for (int t = lane; t < k; t += 32) {
        uint2 v = src[t];
        unsigned col = v.x >> 17;
        unsigned long long val = ((unsigned long long)v.x << 32) | (unsigned long long)v.y;
        unsigned h = col & (TBL - 1);
        while (true) {
            unsigned long long cur = tbl[wid][h];
            if (cur == 0ULL) {
                unsigned long long old = atomicCAS(&tbl[wid][h], 0ULL, val);
                if (old == 0ULL) break;
                cur = old;
            }
            if ((unsigned)(cur >> 49) == col) {       // same col -> keep max priority
                atomicMax(&tbl[wid][h], val);
                break;
            }
            h = (h + 1) & (TBL - 1);
        }
    }
    __syncwarp();

    // compact + degree sum
    float deg = 0.f;
    int base = 0;
    uint2* dst = &g_adj[(size_t)row * MAXK];
    #pragma unroll
    for (int s0 = 0; s0 < TBL; s0 += 32) {
        unsigned long long cur = tbl[wid][s0 + lane];
        bool has = (cur != 0ULL);
        unsigned bal = __ballot_sync(0xFFFFFFFFu, has);
        if (has) {
            int pos = base + __popc(bal & ((1u << lane) - 1));
            unsigned col = ((unsigned)(cur >> 32)) >> 17;
            unsigned mb  = (unsigned)cur;
            dst[pos] = make_uint2(col, mb);
            deg += __uint_as_float(mb);
        }
        base += __popc(bal);
    }
    #pragma unroll
    for (int o = 16; o; o >>= 1) deg += __shfl_down_sync(0xFFFFFFFFu, deg, o);
    if (lane == 0) {
        g_nnz[row] = base;
        g_dis[row] = rsqrtf(fmaxf(1.0f + deg, 1e-6f));
        g_cnt_raw[row] = 0;     // ready for next replay
    }
}

// ---------------------------------------------------------------------------
// prep: g_xh = half(dis ⊙ H)   (1M half2 elements)
__global__ void __launch_bounds__(256) prep_k(const float* __restrict__ H) {
    int t = blockIdx.x * 256 + threadIdx.x;      // t in [0, ROWS*32)
    int row = t >> 5;
    float d = g_dis[row];
    float2 h = ((const float2*)H)[t];
    g_xh[t] = __floats2half2_rn(d * h.x, d * h.y);
}

// ---------------------------------------------------------------------------
// fused layer on pre-scaled X~ = dis ⊙ X (fp16):
//   pre  = sum_e m_e * X~[col] + X~[row]          (fp32 accumulate)
//   v    = (gelu?)((dis_r * pre) @ W^T)           (shuffle GEMM, fp32)
//   stage 0: store half(dis_r * v) to g_xh1 ; stage 1: store fp32 v to out
// Warp per 4 rows; lane owns dims {2l, 2l+1}; rows interleaved, k-unroll x2.
// Internal buffers resolved ON DEVICE (host must not pass __device__ symbols).
__global__ void __launch_bounds__(256) layer_k(const float* __restrict__ Wl,
                                               float* __restrict__ out,
                                               int stage) {
    const __half2* Xin  = (stage == 0) ? g_xh : g_xh1;

    // sW[d*32 + j] = {W[2j][d], W[2j+1][d]}
    __shared__ float2 sW[64 * 32];
    int tid = threadIdx.x;
    for (int idx = tid; idx < 4096; idx += 256) {
        int e = idx >> 6, d = idx & 63;
        ((float*)&sW[d * 32 + (e >> 1)])[e & 1] = Wl[idx];  // coalesced read
    }
    __syncthreads();

    int wid = tid >> 5, lane = tid & 31;
    int row0 = blockIdx.x * 32 + wid * 4;
    const __half2* Xb = Xin + (size_t)(row0 & ~(NN - 1)) * 32;

    int nnz[4];
    const uint2* adj[4];
    float2 a[4];
    float disr[4];
    int kmax = 0;
    #pragma unroll
    for (int r = 0; r < 4; r++) {
        int row = row0 + r;
        nnz[r] = g_nnz[row];
        kmax = max(kmax, nnz[r]);
        adj[r] = &g_adj[(size_t)row * MAXK];
        disr[r] = g_dis[row];
        a[r] = __half22float2(Xin[(size_t)row * 32 + lane]);  // X~row (diag term)
    }

    for (int k = 0; k < kmax; k += 2) {
        uint2 e[4][2];
        #pragma unroll
        for (int r = 0; r < 4; r++)
            #pragma unroll
            for (int j = 0; j < 2; j++) {
                int idx = k + j;
                idx = (idx < nnz[r]) ? idx : 0;
                e[r][j] = __ldg(&adj[r][idx]);
            }
        __half2 x[4][2];
        #pragma unroll
        for (int r = 0; r < 4; r++)
            #pragma unroll
            for (int j = 0; j < 2; j++) {
                unsigned c = e[r][j].x & (NN - 1);     // safety mask
                x[r][j] = Xb[(size_t)c * 32 + lane];
            }
        #pragma unroll
        for (int r = 0; r < 4; r++)
            #pragma unroll
            for (int j = 0; j < 2; j++) {
                float w = (k + j < nnz[r]) ? __uint_as_float(e[r][j].y) : 0.f;
                float2 xf = __half22float2(x[r][j]);
                a[r].x += w * xf.x;
                a[r].y += w * xf.y;
            }
    }
    #pragma unroll
    for (int r = 0; r < 4; r++) { a[r].x *= disr[r]; a[r].y *= disr[r]; }

    // GEMM: v[row][e] = sum_d pre[row][d] * W[e][d]; lane owns e = {2l, 2l+1}
    float2 o[4];
    #pragma unroll
    for (int r = 0; r < 4; r++) { o[r].x = 0.f; o[r].y = 0.f; }

    #pragma unroll
    for (int d = 0; d < 64; d++) {
        float2 w2 = sW[d * 32 + lane];
        int srcl = d >> 1;
        #pragma unroll
        for (int r = 0; r < 4; r++) {
            float xd = __shfl_sync(0xFFFFFFFFu, (d & 1) ? a[r].y : a[r].x, srcl);
            o[r].x += xd * w2.x;
            o[r].y += xd * w2.y;
        }
    }

    #pragma unroll
    for (int r = 0; r < 4; r++) {
        float2 v = o[r];
        size_t idx = (size_t)(row0 + r) * 32 + lane;
        if (stage == 0) {
            // exact GELU
            v.x = 0.5f * v.x * (1.f + erff(v.x * 0.70710678118654752f));
            v.y = 0.5f * v.y * (1.f + erff(v.y * 0.70710678118654752f));
            g_xh1[idx] = __floats2half2_rn(disr[r] * v.x, disr[r] * v.y);
        } else {
            ((float2*)out)[idx] = v;
        }
    }
}

// ---------------------------------------------------------------------------
extern "C" void kernel_launch(void* const* d_in, const int* in_sizes, int n_in,
                              void* d_out, int out_size) {
    const float* H  = (const float*)d_in[0];
    const int*   ei = (const int*)  d_in[1];
    const float* m  = (const float*)d_in[2];
    const float* W  = (const float*)d_in[3];
    float* out = (float*)d_out;

    scatter_k<<<(BB * EE) / 256, 256>>>(ei, m);
    dedup_k<<<ROWS / 8, 256>>>();
    prep_k<<<(ROWS * 32) / 256, 256>>>(H);
    layer_k<<<ROWS / 32, 256>>>(W,           nullptr, 0);   // g_xh -> g_xh1, GELU
    layer_k<<<ROWS / 32, 256>>>(W + DD * DD, out,     1);   // g_xh1 -> out
}

// round 6
// speedup vs baseline: 1.3108x; 1.3060x over previous
#include <cuda_runtime.h>
#include <math.h>

// Problem constants (fixed-shape problem)
#define BB   16
#define NN   2048
#define DD   64
#define EE   32768
#define MAXK 128
#define ROWS (BB*NN)          // 32768
#define TBL  128

// Scratch (device globals; zero-initialized at module load; no allocation)
__device__ int      g_cnt_raw[ROWS];                 // scatter counters (reset by dedup)
__device__ int      g_nnz[ROWS];                     // padded row sizes (multiple of 8)
__device__ uint2    g_bucket[(size_t)ROWS * MAXK];   // 32 MB (col<<17|pri, m_bits)
__device__ float    g_dis[ROWS];
__device__ uint2    g_adj[(size_t)ROWS * MAXK];      // 32 MB (col, m_bits), zero-padded
__device__ float2   g_x [(size_t)ROWS * 32];         // 8 MB: dis ⊙ H   (layer 0 input)
__device__ float2   g_x1[(size_t)ROWS * 32];         // 8 MB: dis ⊙ x1  (layer 1 input)

// ---------------------------------------------------------------------------
// scatter directed entries into per-row buckets, carrying m (coalesced read).
// key = (col << 17) | priority, priority = pass*E + e (pass2 > pass1)
__global__ void scatter_k(const int* __restrict__ ei, const float* __restrict__ m) {
    int t = blockIdx.x * blockDim.x + threadIdx.x;
    int b = t >> 15;
    int e = t & (EE - 1);
    int src = ei[b * 2 * EE + e];
    int dst = ei[b * 2 * EE + EE + e];
    unsigned mbits = __float_as_uint(m[b * EE + e]);

    int r1 = b * NN + src;
    int p1 = atomicAdd(&g_cnt_raw[r1], 1);
    if (p1 < MAXK)
        g_bucket[(size_t)r1 * MAXK + p1] = make_uint2(((unsigned)dst << 17) | (unsigned)e, mbits);

    int r2 = b * NN + dst;
    int p2 = atomicAdd(&g_cnt_raw[r2], 1);
    if (p2 < MAXK)
        g_bucket[(size_t)r2 * MAXK + p2] = make_uint2(((unsigned)src << 17) | (unsigned)(EE + e), mbits);
}

// ---------------------------------------------------------------------------
// O(k) hash dedup (exact .set last-write-wins via 64-bit atomicMax on
// (col<<17|pri) in high word), ballot compaction into zero-padded CSR,
// deg -> dis = rsqrt(deg), AND prep: g_x = dis ⊙ H (fp32).
// Resets g_cnt_raw. One warp per row, 8 rows per block.
__global__ void __launch_bounds__(256) dedup_k(const float* __restrict__ H) {
    __shared__ unsigned long long tbl[8][TBL];
    int wid  = threadIdx.x >> 5, lane = threadIdx.x & 31;
    int row  = blockIdx.x * 8 + wid;

    for (int i = lane; i < TBL; i += 32) tbl[wid][i] = 0ULL;
    __syncwarp();

    int k = g_cnt_raw[row];
    if (k > MAXK) k = MAXK;
    const uint2* src = &g_bucket[(size_t)row * MAXK];
    for (int t = lane; t < k; t += 32) {
        uint2 v = src[t];
        unsigned col = v.x >> 17;
        unsigned long long val = ((unsigned long long)v.x << 32) | (unsigned long long)v.y;
        unsigned h = col & (TBL - 1);
        while (true) {
            unsigned long long cur = tbl[wid][h];
            if (cur == 0ULL) {
                unsigned long long old = atomicCAS(&tbl[wid][h], 0ULL, val);
                if (old == 0ULL) break;
                cur = old;
            }
            if ((unsigned)(cur >> 49) == col) {       // same col -> keep max priority
                atomicMax(&tbl[wid][h], val);
                break;
            }
            h = (h + 1) & (TBL - 1);
        }
    }
    __syncwarp();

    // compact + degree sum
    float deg = 0.f;
    int base = 0;
    uint2* dst = &g_adj[(size_t)row * MAXK];
    #pragma unroll
    for (int s0 = 0; s0 < TBL; s0 += 32) {
        unsigned long long cur = tbl[wid][s0 + lane];
        bool has = (cur != 0ULL);
        unsigned bal = __ballot_sync(0xFFFFFFFFu, has);
        if (has) {
            int pos = base + __popc(bal & ((1u << lane) - 1));
            unsigned col = ((unsigned)(cur >> 32)) >> 17;
            unsigned mb  = (unsigned)cur;
            dst[pos] = make_uint2(col, mb);
            deg += __uint_as_float(mb);
        }
        base += __popc(bal);
    }
    // zero padding up to multiple of 8 (beyond stays zero from static init)
    int pad = (base + 7) & ~7;
    if (base + lane < pad) dst[base + lane] = make_uint2(0u, 0u);

    // all-lanes deg reduction -> dis on every lane
    #pragma unroll
    for (int o = 16; o; o >>= 1) deg += __shfl_xor_sync(0xFFFFFFFFu, deg, o);
    float dis = rsqrtf(fmaxf(1.0f + deg, 1e-6f));

    // prep: g_x[row] = dis * H[row]
    const float2* Hrow = (const float2*)H + row * 32;
    float2 h2 = Hrow[lane];
    g_x[row * 32 + lane] = make_float2(dis * h2.x, dis * h2.y);

    if (lane == 0) {
        g_nnz[row] = pad;
        g_dis[row] = dis;
        g_cnt_raw[row] = 0;     // ready for next replay
    }
}

// ---------------------------------------------------------------------------
// fused layer on pre-scaled X~ = dis ⊙ X (fp32):
//   pre = dis_r * (sum_e m_e * X~[col] + X~[row]);  v = pre @ W^T
//   stage 0: g_x -> g_x1 storing dis_r * gelu(v);  stage 1: g_x1 -> out (raw v)
// Warp per 4 rows; lane owns dims {2l,2l+1}; zero-padded CSR (no predicates);
// adjacency via uniform uint4 (2 edges/LDG.128); 8 gathers in flight per iter.
__global__ void __launch_bounds__(256) layer_k(const float* __restrict__ Wl,
                                               float* __restrict__ out,
                                               int stage) {
    const float2* Xin = (stage == 0) ? g_x : g_x1;

    // sW4[d2*32 + j] = (W[2j][2d2], W[2j+1][2d2], W[2j][2d2+1], W[2j+1][2d2+1])
    __shared__ float4 sW4[32 * 32];
    int tid = threadIdx.x;
    for (int idx = tid; idx < 4096; idx += 256) {
        int e = idx >> 6, d = idx & 63;
        ((float*)sW4)[(d >> 1) * 128 + (e >> 1) * 4 + (d & 1) * 2 + (e & 1)] = Wl[idx];
    }
    __syncthreads();

    int wid = tid >> 5, lane = tid & 31;
    int row0 = blockIdx.x * 32 + wid * 4;
    const float2* Xb = Xin + (row0 & ~(NN - 1)) * 32;   // batch base

    float2 a[4];
    float disr[4];
    const uint2* arow[4];
    int kmax = 0;
    #pragma unroll
    for (int r = 0; r < 4; r++) {
        int row = row0 + r;
        int pn = g_nnz[row];
        kmax = max(kmax, pn);
        arow[r] = &g_adj[(size_t)row * MAXK];
        disr[r] = g_dis[row];
        a[r] = Xin[row * 32 + lane];                    // diag term X~row
    }

    for (int k = 0; k < kmax; k += 2) {
        uint4 av[4];
        #pragma unroll
        for (int r = 0; r < 4; r++)
            av[r] = *(const uint4*)(arow[r] + k);       // uniform, mostly L1-hit
        float2 x[4][2];
        #pragma unroll
        for (int r = 0; r < 4; r++) {
            int c0 = (int)(av[r].x & (NN - 1));
            int c1 = (int)(av[r].z & (NN - 1));
            x[r][0] = Xb[c0 * 32 + lane];
            x[r][1] = Xb[c1 * 32 + lane];
        }
        #pragma unroll
        for (int r = 0; r < 4; r++) {
            float w0 = __uint_as_float(av[r].y);
            float w1 = __uint_as_float(av[r].w);
            a[r].x += w0 * x[r][0].x; a[r].y += w0 * x[r][0].y;
            a[r].x += w1 * x[r][1].x; a[r].y += w1 * x[r][1].y;
        }
    }
    #pragma unroll
    for (int r = 0; r < 4; r++) { a[r].x *= disr[r]; a[r].y *= disr[r]; }

    // GEMM: v[row][e] = sum_d pre[row][d] * W[e][d]; lane owns e = {2l, 2l+1}
    float2 o[4];
    #pragma unroll
    for (int r = 0; r < 4; r++) { o[r].x = 0.f; o[r].y = 0.f; }

    #pragma unroll
    for (int d2 = 0; d2 < 32; d2++) {
        float4 w4 = sW4[d2 * 32 + lane];
        #pragma unroll
        for (int r = 0; r < 4; r++) {
            float xa = __shfl_sync(0xFFFFFFFFu, a[r].x, d2);   // pre[2*d2]
            float xb = __shfl_sync(0xFFFFFFFFu, a[r].y, d2);   // pre[2*d2+1]
            o[r].x += xa * w4.x + xb * w4.z;
            o[r].y += xa * w4.y + xb * w4.w;
        }
    }

    #pragma unroll
    for (int r = 0; r < 4; r++) {
        float2 v = o[r];
        int idx = (row0 + r) * 32 + lane;
        if (stage == 0) {
            // exact GELU, then prescale by dis for next layer's input
            v.x = 0.5f * v.x * (1.f + erff(v.x * 0.70710678118654752f));
            v.y = 0.5f * v.y * (1.f + erff(v.y * 0.70710678118654752f));
            float d = disr[r];
            g_x1[idx] = make_float2(d * v.x, d * v.y);
        } else {
            ((float2*)out)[idx] = v;
        }
    }
}

// ---------------------------------------------------------------------------
extern "C" void kernel_launch(void* const* d_in, const int* in_sizes, int n_in,
                              void* d_out, int out_size) {
    const float* H  = (const float*)d_in[0];
    const int*   ei = (const int*)  d_in[1];
    const float* m  = (const float*)d_in[2];
    const float* W  = (const float*)d_in[3];
    float* out = (float*)d_out;

    scatter_k<<<(BB * EE) / 256, 256>>>(ei, m);
    dedup_k<<<ROWS / 8, 256>>>(H);
    layer_k<<<ROWS / 32, 256>>>(W,           nullptr, 0);   // g_x  -> g_x1, GELU
    layer_k<<<ROWS / 32, 256>>>(W + DD * DD, out,     1);   // g_x1 -> out
}

// round 7
// speedup vs baseline: 1.3975x; 1.0661x over previous
#include <cuda_runtime.h>
#include <cuda_fp16.h>
#include <math.h>

// Problem constants (fixed-shape problem)
#define BB   16
#define NN   2048
#define DD   64
#define EE   32768
#define MAXK 128
#define ROWS (BB*NN)          // 32768
#define TBL  128

// Scratch (device globals; zero-initialized at module load; no allocation)
__device__ int      g_cnt_raw[ROWS];                 // scatter counters (reset by dedup)
__device__ int      g_nnz[ROWS];                     // padded row sizes (multiple of 8)
__device__ uint2    g_bucket[(size_t)ROWS * MAXK];   // 32 MB (col<<17|pri, m_bits)
__device__ float    g_dis[ROWS];
__device__ uint2    g_adj[(size_t)ROWS * MAXK];      // 32 MB (col<<7 byte-off, m_bits)
__device__ __half2  g_x [(size_t)ROWS * 32];         // 4 MB: dis ⊙ H   (layer 0 input)
__device__ __half2  g_x1[(size_t)ROWS * 32];         // 4 MB: dis ⊙ x1  (layer 1 input)

// ---------------------------------------------------------------------------
// scatter directed entries into per-row buckets, carrying m (coalesced read).
// key = (col << 17) | priority, priority = pass*E + e (pass2 > pass1)
__global__ void scatter_k(const int* __restrict__ ei, const float* __restrict__ m) {
    int t = blockIdx.x * blockDim.x + threadIdx.x;
    int b = t >> 15;
    int e = t & (EE - 1);
    int src = ei[b * 2 * EE + e];
    int dst = ei[b * 2 * EE + EE + e];
    unsigned mbits = __float_as_uint(m[t]);

    int r1 = b * NN + src;
    int p1 = atomicAdd(&g_cnt_raw[r1], 1);
    if (p1 < MAXK)
        g_bucket[(size_t)r1 * MAXK + p1] = make_uint2(((unsigned)dst << 17) | (unsigned)e, mbits);

    int r2 = b * NN + dst;
    int p2 = atomicAdd(&g_cnt_raw[r2], 1);
    if (p2 < MAXK)
        g_bucket[(size_t)r2 * MAXK + p2] = make_uint2(((unsigned)src << 17) | (unsigned)(EE + e), mbits);
}

// ---------------------------------------------------------------------------
// O(k) hash dedup (exact .set last-write-wins via 64-bit atomicMax on
// (col<<17|pri) in high word), ballot compaction into zero-padded CSR storing
// BYTE OFFSETS (col*128), deg -> dis = rsqrt(deg), AND prep: g_x = half(dis ⊙ H).
// Resets g_cnt_raw. One warp per row, 8 rows per block.
__global__ void __launch_bounds__(256) dedup_k(const float* __restrict__ H) {
    __shared__ unsigned long long tbl[8][TBL];
    int wid  = threadIdx.x >> 5, lane = threadIdx.x & 31;
    int row  = blockIdx.x * 8 + wid;

    for (int i = lane; i < TBL; i += 32) tbl[wid][i] = 0ULL;
    __syncwarp();

    int k = g_cnt_raw[row];
    if (k > MAXK) k = MAXK;
    const uint2* src = &g_bucket[(size_t)row * MAXK];
    for (int t = lane; t < k; t += 32) {
        uint2 v = src[t];
        unsigned col = v.x >> 17;
        unsigned long long val = ((unsigned long long)v.x << 32) | (unsigned long long)v.y;
        unsigned h = col & (TBL - 1);
        while (true) {
            unsigned long long cur = tbl[wid][h];
            if (cur == 0ULL) {
                unsigned long long old = atomicCAS(&tbl[wid][h], 0ULL, val);
                if (old == 0ULL) break;
                cur = old;
            }
            if ((unsigned)(cur >> 49) == col) {       // same col -> keep max priority
                atomicMax(&tbl[wid][h], val);
                break;
            }
            h = (h + 1) & (TBL - 1);
        }
    }
    __syncwarp();

    // compact + degree sum; store byte offset col*128 (fp16 row = 128B)
    float deg = 0.f;
    int base = 0;
    uint2* dst = &g_adj[(size_t)row * MAXK];
    #pragma unroll
    for (int s0 = 0; s0 < TBL; s0 += 32) {
        unsigned long long cur = tbl[wid][s0 + lane];
        bool has = (cur != 0ULL);
        unsigned bal = __ballot_sync(0xFFFFFFFFu, has);
        if (has) {
            int pos = base + __popc(bal & ((1u << lane) - 1));
            unsigned col = ((unsigned)(cur >> 32)) >> 17;
            unsigned mb  = (unsigned)cur;
            dst[pos] = make_uint2(col << 7, mb);
            deg += __uint_as_float(mb);
        }
        base += __popc(bal);
    }
    // zero padding up to multiple of 8 (beyond stays zero from static init;
    // replays rewrite identical data so zero region is invariant)
    int pad = (base + 7) & ~7;
    if (base + lane < pad) dst[base + lane] = make_uint2(0u, 0u);

    // all-lanes deg reduction -> dis on every lane
    #pragma unroll
    for (int o = 16; o; o >>= 1) deg += __shfl_xor_sync(0xFFFFFFFFu, deg, o);
    float dis = rsqrtf(fmaxf(1.0f + deg, 1e-6f));

    // prep: g_x[row] = half(dis * H[row])
    const float2* Hrow = (const float2*)H + row * 32;
    float2 h2 = Hrow[lane];
    g_x[row * 32 + lane] = __floats2half2_rn(dis * h2.x, dis * h2.y);

    if (lane == 0) {
        g_nnz[row] = pad;
        g_dis[row] = dis;
        g_cnt_raw[row] = 0;     // ready for next replay
    }
}

// ---------------------------------------------------------------------------
// fused layer on pre-scaled X~ = dis ⊙ X (fp16 storage, fp32 math):
//   pre = dis_r * (sum_e m_e * X~[col] + X~[row]);  v = pre @ W^T
//   stage 0: g_x -> g_x1 storing half(dis_r * gelu(v)); stage 1: g_x1 -> out
// Warp per 4 rows; lane owns dims {2l,2l+1}; zero-padded CSR; byte-offset
// adjacency (no per-edge IMAD/mask); 1 L1 wavefront per edge gather.
__global__ void __launch_bounds__(256) layer_k(const float* __restrict__ Wl,
                                               float* __restrict__ out,
                                               int stage) {
    const __half2* Xin = (stage == 0) ? g_x : g_x1;

    // sW4[d2*32 + j] = (W[2j][2d2], W[2j+1][2d2], W[2j][2d2+1], W[2j+1][2d2+1])
    __shared__ float4 sW4[32 * 32];
    int tid = threadIdx.x;
    for (int idx = tid; idx < 4096; idx += 256) {
        int e = idx >> 6, d = idx & 63;
        ((float*)sW4)[(d >> 1) * 128 + (e >> 1) * 4 + (d & 1) * 2 + (e & 1)] = Wl[idx];
    }
    __syncthreads();

    int wid = tid >> 5, lane = tid & 31;
    int row0 = blockIdx.x * 32 + wid * 4;
    // batch base as byte pointer; lane's fixed byte offset folded in once
    const char* XbL = (const char*)(Xin + (row0 & ~(NN - 1)) * 32) + lane * 4;

    float2 a[4];
    float disr[4];
    const uint2* arow[4];
    int kmax = 0;
    #pragma unroll
    for (int r = 0; r < 4; r++) {
        int row = row0 + r;
        int pn = g_nnz[row];
        kmax = max(kmax, pn);
        arow[r] = &g_adj[(size_t)row * MAXK];
        disr[r] = g_dis[row];
        a[r] = __half22float2(Xin[row * 32 + lane]);    // diag term X~row
    }

    for (int k = 0; k < kmax; k += 2) {
        uint4 av[4];
        #pragma unroll
        for (int r = 0; r < 4; r++)
            av[r] = *(const uint4*)(arow[r] + k);       // uniform, mostly L1-hit
        __half2 x[4][2];
        #pragma unroll
        for (int r = 0; r < 4; r++) {
            x[r][0] = *(const __half2*)(XbL + av[r].x);
            x[r][1] = *(const __half2*)(XbL + av[r].z);
        }
        #pragma unroll
        for (int r = 0; r < 4; r++) {
            float w0 = __uint_as_float(av[r].y);
            float w1 = __uint_as_float(av[r].w);
            float2 x0 = __half22float2(x[r][0]);
            float2 x1 = __half22float2(x[r][1]);
            a[r].x += w0 * x0.x; a[r].y += w0 * x0.y;
            a[r].x += w1 * x1.x; a[r].y += w1 * x1.y;
        }
    }
    #pragma unroll
    for (int r = 0; r < 4; r++) { a[r].x *= disr[r]; a[r].y *= disr[r]; }

    // GEMM: v[row][e] = sum_d pre[row][d] * W[e][d]; lane owns e = {2l, 2l+1}
    float2 o[4];
    #pragma unroll
    for (int r = 0; r < 4; r++) { o[r].x = 0.f; o[r].y = 0.f; }

    #pragma unroll
    for (int d2 = 0; d2 < 32; d2++) {
        float4 w4 = sW4[d2 * 32 + lane];
        #pragma unroll
        for (int r = 0; r < 4; r++) {
            float xa = __shfl_sync(0xFFFFFFFFu, a[r].x, d2);   // pre[2*d2]
            float xb = __shfl_sync(0xFFFFFFFFu, a[r].y, d2);   // pre[2*d2+1]
            o[r].x += xa * w4.x + xb * w4.z;
            o[r].y += xa * w4.y + xb * w4.w;
        }
    }

    #pragma unroll
    for (int r = 0; r < 4; r++) {
        float2 v = o[r];
        int idx = (row0 + r) * 32 + lane;
        if (stage == 0) {
            // exact GELU, then prescale by dis for next layer's input
            v.x = 0.5f * v.x * (1.f + erff(v.x * 0.70710678118654752f));
            v.y = 0.5f * v.y * (1.f + erff(v.y * 0.70710678118654752f));
            float d = disr[r];
            g_x1[idx] = __floats2half2_rn(d * v.x, d * v.y);
        } else {
            ((float2*)out)[idx] = v;
        }
    }
}

// ---------------------------------------------------------------------------
extern "C" void kernel_launch(void* const* d_in, const int* in_sizes, int n_in,
                              void* d_out, int out_size) {
    const float* H  = (const float*)d_in[0];
    const int*   ei = (const int*)  d_in[1];
    const float* m  = (const float*)d_in[2];
    const float* W  = (const float*)d_in[3];
    float* out = (float*)d_out;

    scatter_k<<<(BB * EE) / 256, 256>>>(ei, m);
    dedup_k<<<ROWS / 8, 256>>>(H);
    layer_k<<<ROWS / 32, 256>>>(W,           nullptr, 0);   // g_x  -> g_x1, GELU
    layer_k<<<ROWS / 32, 256>>>(W + DD * DD, out,     1);   // g_x1 -> out
}

// round 8
// speedup vs baseline: 2.0000x; 1.4312x over previous
#include <cuda_runtime.h>
#include <cuda_fp16.h>
#include <math.h>

// Problem constants (fixed-shape problem)
#define BB   16
#define NN   2048
#define DD   64
#define EE   32768
#define MAXK 128
#define ROWS (BB*NN)          // 32768
#define TBL  128
#define BR   64               // rows per gemm block

// Scratch (device globals; zero-initialized at module load; no allocation)
__device__ int      g_cnt_raw[ROWS];                 // scatter counters (reset by dedup)
__device__ int      g_nnz[ROWS];                     // padded row sizes (multiple of 8)
__device__ uint2    g_bucket[(size_t)ROWS * MAXK];   // 32 MB (col<<17|pri, m_bits)
__device__ float    g_dis[ROWS];
__device__ uint2    g_adj[(size_t)ROWS * MAXK];      // 32 MB (col<<7 byte-off, m_bits)
__device__ __half2  g_x [(size_t)ROWS * 32];         // 4 MB: dis ⊙ H   (layer 0 input)
__device__ __half2  g_x1[(size_t)ROWS * 32];         // 4 MB: dis ⊙ x1  (layer 1 input)
__device__ float2   g_pre[(size_t)ROWS * 32];        // 8 MB: dis_r * (A·X~ + X~row)

// ---- packed f32x2 helpers (Blackwell) --------------------------------------
__device__ __forceinline__ unsigned long long splat2(float x) {
    unsigned long long r;
    asm("mov.b64 %0, {%1, %1};" : "=l"(r) : "r"(__float_as_uint(x)));
    return r;
}
__device__ __forceinline__ void fma2(unsigned long long& d,
                                     unsigned long long a, unsigned long long b) {
    asm("fma.rn.f32x2 %0, %1, %2, %0;" : "+l"(d) : "l"(a), "l"(b));
}
__device__ __forceinline__ float2 unpack2(unsigned long long v) {
    unsigned lo, hi;
    asm("mov.b64 {%0, %1}, %2;" : "=r"(lo), "=r"(hi) : "l"(v));
    return make_float2(__uint_as_float(lo), __uint_as_float(hi));
}

// ---------------------------------------------------------------------------
// scatter directed entries into per-row buckets, carrying m (coalesced read).
// key = (col << 17) | priority, priority = pass*E + e (pass2 > pass1)
__global__ void scatter_k(const int* __restrict__ ei, const float* __restrict__ m) {
    int t = blockIdx.x * blockDim.x + threadIdx.x;
    int b = t >> 15;
    int e = t & (EE - 1);
    int src = ei[b * 2 * EE + e];
    int dst = ei[b * 2 * EE + EE + e];
    unsigned mbits = __float_as_uint(m[t]);

    int r1 = b * NN + src;
    int p1 = atomicAdd(&g_cnt_raw[r1], 1);
    if (p1 < MAXK)
        g_bucket[(size_t)r1 * MAXK + p1] = make_uint2(((unsigned)dst << 17) | (unsigned)e, mbits);

    int r2 = b * NN + dst;
    int p2 = atomicAdd(&g_cnt_raw[r2], 1);
    if (p2 < MAXK)
        g_bucket[(size_t)r2 * MAXK + p2] = make_uint2(((unsigned)src << 17) | (unsigned)(EE + e), mbits);
}

// ---------------------------------------------------------------------------
// O(k) hash dedup (exact .set last-write-wins via 64-bit atomicMax on
// (col<<17|pri) in high word), ballot compaction into zero-padded CSR storing
// BYTE OFFSETS (col*128), deg -> dis = rsqrt(deg), AND prep: g_x = half(dis ⊙ H).
// Resets g_cnt_raw. One warp per row, 8 rows per block.
__global__ void __launch_bounds__(256) dedup_k(const float* __restrict__ H) {
    __shared__ unsigned long long tbl[8][TBL];
    int wid  = threadIdx.x >> 5, lane = threadIdx.x & 31;
    int row  = blockIdx.x * 8 + wid;

    for (int i = lane; i < TBL; i += 32) tbl[wid][i] = 0ULL;
    __syncwarp();

    int k = g_cnt_raw[row];
    if (k > MAXK) k = MAXK;
    const uint2* src = &g_bucket[(size_t)row * MAXK];
    for (int t = lane; t < k; t += 32) {
        uint2 v = src[t];
        unsigned col = v.x >> 17;
        unsigned long long val = ((unsigned long long)v.x << 32) | (unsigned long long)v.y;
        unsigned h = col & (TBL - 1);
        while (true) {
            unsigned long long cur = tbl[wid][h];
            if (cur == 0ULL) {
                unsigned long long old = atomicCAS(&tbl[wid][h], 0ULL, val);
                if (old == 0ULL) break;
                cur = old;
            }
            if ((unsigned)(cur >> 49) == col) {       // same col -> keep max priority
                atomicMax(&tbl[wid][h], val);
                break;
            }
            h = (h + 1) & (TBL - 1);
        }
    }
    __syncwarp();

    // compact + degree sum; store byte offset col*128 (fp16 row = 128B)
    float deg = 0.f;
    int base = 0;
    uint2* dst = &g_adj[(size_t)row * MAXK];
    #pragma unroll
    for (int s0 = 0; s0 < TBL; s0 += 32) {
        unsigned long long cur = tbl[wid][s0 + lane];
        bool has = (cur != 0ULL);
        unsigned bal = __ballot_sync(0xFFFFFFFFu, has);
        if (has) {
            int pos = base + __popc(bal & ((1u << lane) - 1));
            unsigned col = ((unsigned)(cur >> 32)) >> 17;
            unsigned mb  = (unsigned)cur;
            dst[pos] = make_uint2(col << 7, mb);
            deg += __uint_as_float(mb);
        }
        base += __popc(bal);
    }
    // zero padding up to multiple of 8 (beyond stays zero from static init;
    // replays rewrite identical data so zero region is invariant)
    int pad = (base + 7) & ~7;
    if (base + lane < pad) dst[base + lane] = make_uint2(0u, 0u);

    // all-lanes deg reduction -> dis on every lane
    #pragma unroll
    for (int o = 16; o; o >>= 1) deg += __shfl_xor_sync(0xFFFFFFFFu, deg, o);
    float dis = rsqrtf(fmaxf(1.0f + deg, 1e-6f));

    // prep: g_x[row] = half(dis * H[row])
    const float2* Hrow = (const float2*)H + row * 32;
    float2 h2 = Hrow[lane];
    g_x[row * 32 + lane] = __floats2half2_rn(dis * h2.x, dis * h2.y);

    if (lane == 0) {
        g_nnz[row] = pad;
        g_dis[row] = dis;
        g_cnt_raw[row] = 0;     // ready for next replay
    }
}

// ---------------------------------------------------------------------------
// SpMM phase: pre[row] = dis_r * (sum_e m_e * X~[col] + X~[row]).
// One warp per row, k-unrolled x8 -> 8 gathers + 4 uniform LDG.128 in flight.
// fp16 X storage, fp32 accumulate; writes fp32 pre coalesced.
__global__ void __launch_bounds__(256) spmm_k(int stage) {
    const __half2* Xin = (stage == 0) ? g_x : g_x1;
    int wid = threadIdx.x >> 5, lane = threadIdx.x & 31;
    int row = blockIdx.x * 8 + wid;

    const char* XbL = (const char*)(Xin + (row & ~(NN - 1)) * 32) + lane * 4;
    float2 a = __half22float2(Xin[row * 32 + lane]);    // diag term X~row
    int n = g_nnz[row];                                  // multiple of 8
    const uint2* arow = &g_adj[(size_t)row * MAXK];

    for (int k = 0; k < n; k += 8) {
        uint4 e0 = *(const uint4*)(arow + k);
        uint4 e1 = *(const uint4*)(arow + k + 2);
        uint4 e2 = *(const uint4*)(arow + k + 4);
        uint4 e3 = *(const uint4*)(arow + k + 6);
        __half2 x0 = *(const __half2*)(XbL + e0.x);
        __half2 x1 = *(const __half2*)(XbL + e0.z);
        __half2 x2 = *(const __half2*)(XbL + e1.x);
        __half2 x3 = *(const __half2*)(XbL + e1.z);
        __half2 x4 = *(const __half2*)(XbL + e2.x);
        __half2 x5 = *(const __half2*)(XbL + e2.z);
        __half2 x6 = *(const __half2*)(XbL + e3.x);
        __half2 x7 = *(const __half2*)(XbL + e3.z);

        float2 f0 = __half22float2(x0), f1 = __half22float2(x1);
        float2 f2 = __half22float2(x2), f3 = __half22float2(x3);
        float2 f4 = __half22float2(x4), f5 = __half22float2(x5);
        float2 f6 = __half22float2(x6), f7 = __half22float2(x7);
        float w0 = __uint_as_float(e0.y), w1 = __uint_as_float(e0.w);
        float w2 = __uint_as_float(e1.y), w3 = __uint_as_float(e1.w);
        float w4 = __uint_as_float(e2.y), w5 = __uint_as_float(e2.w);
        float w6 = __uint_as_float(e3.y), w7 = __uint_as_float(e3.w);
        a.x += w0 * f0.x; a.y += w0 * f0.y;
        a.x += w1 * f1.x; a.y += w1 * f1.y;
        a.x += w2 * f2.x; a.y += w2 * f2.y;
        a.x += w3 * f3.x; a.y += w3 * f3.y;
        a.x += w4 * f4.x; a.y += w4 * f4.y;
        a.x += w5 * f5.x; a.y += w5 * f5.y;
        a.x += w6 * f6.x; a.y += w6 * f6.y;
        a.x += w7 * f7.x; a.y += w7 * f7.y;
    }
    float dis = g_dis[row];
    g_pre[row * 32 + lane] = make_float2(dis * a.x, dis * a.y);
}

// ---------------------------------------------------------------------------
// Dense GEMM phase: v = pre @ W^T, then (stage 0) g_x1 = half(dis * gelu(v))
// or (stage 1) out = v. 64 rows/block, 256 threads, thread owns 4x4 outputs,
// packed fma.rn.f32x2 inner loop.
__global__ void __launch_bounds__(256) gemm_k(const float* __restrict__ Wl,
                                              float* __restrict__ out,
                                              int stage) {
    __shared__ float sP[BR][68];    // pre tile, row-major [r][d], padded
    __shared__ float sW[64][68];    // W transposed [d][e], padded
    int tid = threadIdx.x;
    int row0 = blockIdx.x * BR;

    // W[e][d] -> sW[d][e]  (coalesced gmem read)
    for (int idx = tid; idx < 4096; idx += 256) {
        int e = idx >> 6, d = idx & 63;
        sW[d][e] = Wl[idx];
    }
    // pre tile: straight float4 copy (row-major, no transpose)
    const float4* P = (const float4*)(g_pre + (size_t)row0 * 32);
    for (int idx = tid; idx < BR * 16; idx += 256) {
        int r = idx >> 4, d4 = idx & 15;
        *(float4*)&sP[r][d4 * 4] = P[idx];
    }
    __syncthreads();

    int rg = tid >> 4, cg = tid & 15;
    int r0 = rg * 4, c0 = cg * 4;

    unsigned long long acc[4][2];
    #pragma unroll
    for (int r = 0; r < 4; r++) { acc[r][0] = 0ULL; acc[r][1] = 0ULL; }

    #pragma unroll
    for (int d0 = 0; d0 < 64; d0 += 4) {
        float4 p[4];
        #pragma unroll
        for (int r = 0; r < 4; r++)
            p[r] = *(const float4*)&sP[r0 + r][d0];
        #pragma unroll
        for (int dd = 0; dd < 4; dd++) {
            unsigned long long w01 = *(const unsigned long long*)&sW[d0 + dd][c0];
            unsigned long long w23 = *(const unsigned long long*)&sW[d0 + dd][c0 + 2];
            #pragma unroll
            for (int r = 0; r < 4; r++) {
                unsigned long long s = splat2((&p[r].x)[dd]);
                fma2(acc[r][0], s, w01);
                fma2(acc[r][1], s, w23);
            }
        }
    }

    #pragma unroll
    for (int r = 0; r < 4; r++) {
        int row = row0 + r0 + r;
        float2 v01 = unpack2(acc[r][0]);
        float2 v23 = unpack2(acc[r][1]);
        if (stage == 0) {
            // exact GELU, prescale by dis, store fp16 for next layer's gather
            float dis = g_dis[row];
            v01.x = 0.5f * v01.x * (1.f + erff(v01.x * 0.70710678118654752f));
            v01.y = 0.5f * v01.y * (1.f + erff(v01.y * 0.70710678118654752f));
            v23.x = 0.5f * v23.x * (1.f + erff(v23.x * 0.70710678118654752f));
            v23.y = 0.5f * v23.y * (1.f + erff(v23.y * 0.70710678118654752f));
            g_x1[row * 32 + (c0 >> 1)]     = __floats2half2_rn(dis * v01.x, dis * v01.y);
            g_x1[row * 32 + (c0 >> 1) + 1] = __floats2half2_rn(dis * v23.x, dis * v23.y);
        } else {
            float4 o = make_float4(v01.x, v01.y, v23.x, v23.y);
            *(float4*)&out[(size_t)row * 64 + c0] = o;
        }
    }
}

// ---------------------------------------------------------------------------
extern "C" void kernel_launch(void* const* d_in, const int* in_sizes, int n_in,
                              void* d_out, int out_size) {
    const float* H  = (const float*)d_in[0];
    const int*   ei = (const int*)  d_in[1];
    const float* m  = (const float*)d_in[2];
    const float* W  = (const float*)d_in[3];
    float* out = (float*)d_out;

    scatter_k<<<(BB * EE) / 256, 256>>>(ei, m);
    dedup_k<<<ROWS / 8, 256>>>(H);
    spmm_k<<<ROWS / 8, 256>>>(0);                       // g_x  -> g_pre
    gemm_k<<<ROWS / BR, 256>>>(W, nullptr, 0);          // g_pre -> g_x1 (GELU)
    spmm_k<<<ROWS / 8, 256>>>(1);                       // g_x1 -> g_pre
    gemm_k<<<ROWS / BR, 256>>>(W + DD * DD, out, 1);    // g_pre -> out
}